// round 1
// baseline (speedup 1.0000x reference)
#include <cuda_runtime.h>
#include <cstdint>

#define N_STEPS 1000

// Per-step fwd keys [0..999] + reverse key [1000], computed on device each call.
__device__ uint2 g_keys[N_STEPS + 1];

// ---------------- Threefry-2x32, 20 rounds (matches jax._src.prng) ----------------
__device__ __forceinline__ void tf_round(uint32_t& x0, uint32_t& x1, int r) {
    x0 += x1;
    x1 = __funnelshift_l(x1, x1, r);  // rotl32(x1, r)
    x1 ^= x0;
}

__device__ __forceinline__ void threefry2x32(uint32_t k0, uint32_t k1,
                                             uint32_t c0, uint32_t c1,
                                             uint32_t& o0, uint32_t& o1) {
    const uint32_t k2 = k0 ^ k1 ^ 0x1BD11BDAu;
    uint32_t x0 = c0 + k0;
    uint32_t x1 = c1 + k1;
    tf_round(x0, x1, 13); tf_round(x0, x1, 15); tf_round(x0, x1, 26); tf_round(x0, x1, 6);
    x0 += k1; x1 += k2 + 1u;
    tf_round(x0, x1, 17); tf_round(x0, x1, 29); tf_round(x0, x1, 16); tf_round(x0, x1, 24);
    x0 += k2; x1 += k0 + 2u;
    tf_round(x0, x1, 13); tf_round(x0, x1, 15); tf_round(x0, x1, 26); tf_round(x0, x1, 6);
    x0 += k0; x1 += k1 + 3u;
    tf_round(x0, x1, 17); tf_round(x0, x1, 29); tf_round(x0, x1, 16); tf_round(x0, x1, 24);
    x0 += k1; x1 += k2 + 4u;
    tf_round(x0, x1, 13); tf_round(x0, x1, 15); tf_round(x0, x1, 26); tf_round(x0, x1, 6);
    o0 = x0 + k2;
    o1 = x1 + k0 + 5u;
}

// fwd_keys[t] = threefry(key=(0,1), counter=(0,t))   [partitionable fold-like split]
// rev_key    = threefry(key=(0,2), counter=(0,999))  [fold_in(key(2), 999)]
__global__ void prep_keys_kernel() {
    int t = threadIdx.x;
    if (t > N_STEPS) return;
    uint32_t k1 = (t < N_STEPS) ? 1u : 2u;
    uint32_t c1 = (t < N_STEPS) ? (uint32_t)t : 999u;
    uint32_t o0, o1;
    threefry2x32(0u, k1, 0u, c1, o0, o1);
    g_keys[t] = make_uint2(o0, o1);
}

// 32 random bits -> 0.1 * sqrt(2) * erfinv(uniform(lo, 1))   (XLA ErfInv32 / Giles poly)
__device__ __forceinline__ float bits_to_noise(uint32_t b) {
    float f = __uint_as_float((b >> 9) | 0x3f800000u);   // [1, 2)
    float u = f - 1.0f;                                  // [0, 1), exact
    float xx = fmaf(u, 2.0f, -0.99999994f);              // uniform in [nextafter(-1,0), 1)
    float w = __log2f(fmaf(xx, -xx, 1.0f)) * -0.69314718f;  // -ln(1 - x^2)
    float p;
    if (w < 5.0f) {
        float z = w - 2.5f;
        p = 2.81022636e-08f;
        p = fmaf(p, z, 3.43273939e-07f);
        p = fmaf(p, z, -3.5233877e-06f);
        p = fmaf(p, z, -4.39150654e-06f);
        p = fmaf(p, z, 0.00021858087f);
        p = fmaf(p, z, -0.00125372503f);
        p = fmaf(p, z, -0.00417768164f);
        p = fmaf(p, z, 0.246640727f);
        p = fmaf(p, z, 1.50140941f);
    } else {
        float z = __fsqrt_rn(w) - 3.0f;
        p = -0.000200214257f;
        p = fmaf(p, z, 0.000100950558f);
        p = fmaf(p, z, 0.00134934322f);
        p = fmaf(p, z, -0.00367342844f);
        p = fmaf(p, z, 0.00573950773f);
        p = fmaf(p, z, -0.0076224613f);
        p = fmaf(p, z, 0.00943887047f);
        p = fmaf(p, z, 1.00167406f);
        p = fmaf(p, z, 2.83297682f);
    }
    return 0.14142136f * (p * xx);   // 0.1 * sqrt(2) folded
}

__global__ void __launch_bounds__(256)
diffusion_kernel(const float* __restrict__ x, float* __restrict__ out, int n) {
    __shared__ uint2 skeys[N_STEPS + 1];
    for (int i = threadIdx.x; i <= N_STEPS; i += 256)
        skeys[i] = g_keys[i];
    __syncthreads();

    unsigned tid  = blockIdx.x * 256u + threadIdx.x;
    unsigned base = tid * 4u;
    if (base >= (unsigned)n) return;

    if (base + 4u <= (unsigned)n) {
        // ---- main vectorized path: 4 independent elements per thread (ILP) ----
        float4 v4 = *reinterpret_cast<const float4*>(x + base);
        float vv[4] = {v4.x, v4.y, v4.z, v4.w};

        #pragma unroll 1
        for (int t = 0; t < N_STEPS; ++t) {
            uint2 k = skeys[t];
            #pragma unroll
            for (int j = 0; j < 4; ++j) {
                uint32_t o0, o1;
                threefry2x32(k.x, k.y, 0u, base + (uint32_t)j, o0, o1);
                vv[j] = __saturatef(vv[j] + bits_to_noise(o0 ^ o1));
            }
        }
        // reverse diffusion: single denoise step
        {
            uint2 k = skeys[N_STEPS];
            #pragma unroll
            for (int j = 0; j < 4; ++j) {
                uint32_t o0, o1;
                threefry2x32(k.x, k.y, 0u, base + (uint32_t)j, o0, o1);
                vv[j] = __saturatef(vv[j] - bits_to_noise(o0 ^ o1));
            }
        }
        *reinterpret_cast<float4*>(out + base) = make_float4(vv[0], vv[1], vv[2], vv[3]);
    } else {
        // ---- tail path (not hit for the expected 25165824-element shape) ----
        for (unsigned e = base; e < (unsigned)n; ++e) {
            float vv = x[e];
            #pragma unroll 1
            for (int t = 0; t < N_STEPS; ++t) {
                uint2 k = skeys[t];
                uint32_t o0, o1;
                threefry2x32(k.x, k.y, 0u, e, o0, o1);
                vv = __saturatef(vv + bits_to_noise(o0 ^ o1));
            }
            uint2 k = skeys[N_STEPS];
            uint32_t o0, o1;
            threefry2x32(k.x, k.y, 0u, e, o0, o1);
            out[e] = __saturatef(vv - bits_to_noise(o0 ^ o1));
        }
    }
}

extern "C" void kernel_launch(void* const* d_in, const int* in_sizes, int n_in,
                              void* d_out, int out_size) {
    const float* x = (const float*)d_in[0];
    float* out     = (float*)d_out;
    int n = out_size;

    prep_keys_kernel<<<1, 1024>>>();

    unsigned threads = (unsigned)((n + 3) / 4);
    unsigned blocks  = (threads + 255u) / 256u;
    diffusion_kernel<<<blocks, 256>>>(x, out, n);
}